// round 2
// baseline (speedup 1.0000x reference)
#include <cuda_runtime.h>

#define B_N   1024
#define D_N   64
#define Q_N   32
#define M_N   4096
#define U_N   64
#define K_TOP 16
#define SCALE_A 0.0125f   /* 0.1 / sqrt(64) */

// Scratch (allocation-free rule: __device__ globals)
__device__ float g_xn[B_N * D_N];     // L2-normalized x
__device__ float g_kinv[Q_N * M_N];   // 1 / ||K[q,m,:]||

// ---------------------------------------------------------------------------
// Prologue 1: normalize x rows. One warp per row.
// ---------------------------------------------------------------------------
__global__ void norm_x_kernel(const float* __restrict__ x) {
    int row  = blockIdx.x * 8 + (threadIdx.x >> 5);
    int lane = threadIdx.x & 31;
    float a = x[row * 64 + lane];
    float b = x[row * 64 + lane + 32];
    float s = a * a + b * b;
    #pragma unroll
    for (int o = 16; o; o >>= 1) s += __shfl_xor_sync(0xffffffffu, s, o);
    float inv = 1.0f / fmaxf(sqrtf(s), 1e-12f);
    g_xn[row * 64 + lane]      = a * inv;
    g_xn[row * 64 + lane + 32] = b * inv;
}

// ---------------------------------------------------------------------------
// Prologue 2: inverse norms of K rows. One warp per (q,m) row.
// ---------------------------------------------------------------------------
__global__ void kinv_kernel(const float* __restrict__ K) {
    int row  = blockIdx.x * 8 + (threadIdx.x >> 5);
    int lane = threadIdx.x & 31;
    float a = K[row * 64 + lane];
    float b = K[row * 64 + lane + 32];
    float s = a * a + b * b;
    #pragma unroll
    for (int o = 16; o; o >>= 1) s += __shfl_xor_sync(0xffffffffu, s, o);
    if (lane == 0) g_kinv[row] = 1.0f / fmaxf(sqrtf(s), 1e-12f);
}

// ---------------------------------------------------------------------------
// Main fused kernel: grid (8 b-tiles, 32 q), 256 threads.
// CTA computes responses[128 b x 4096 m] for one q in 128-wide m tiles with
// 8x8 register micro-tiles, streams a sorted top-16 per b-row in smem, then
// does softmax + M-gather-combine.
//
// Smem (dynamic, floats):
//   Xs [64][128]  swizzled transposed x-tile     (8192)
//   Ks [64][128]  swizzled transposed K-tile,    (8192)  pre-scaled by g_kinv
//   tv [128][16]  top-16 values, sorted desc     (2048)
//   ti [128][16]  top-16 m-indices               (2048 ints)
//
// Swizzle: element (d, m) lives at word d*128 + (((m>>2) ^ ((d>>2)&7))<<2) + (m&3).
// Compute-path LDS.128 is conflict-free; transpose STS is 2-way.
// ---------------------------------------------------------------------------
__global__ __launch_bounds__(256, 2) void cnu_main_kernel(
    const float* __restrict__ Kg,   // [Q, M, D]
    const float* __restrict__ Mg,   // [Q, M, U]
    float* __restrict__ out)        // [B, Q, U]
{
    extern __shared__ float sm[];
    float* Xs = sm;                   // 8192
    float* Ks = sm + 8192;            // 8192
    float* tv = sm + 16384;           // 2048
    int*   ti = (int*)(sm + 18432);   // 2048

    const int tid  = threadIdx.x;
    const int q    = blockIdx.y;
    const int b0   = blockIdx.x * 128;
    const int tx   = tid & 15;
    const int ty   = tid >> 4;
    const int lane = tid & 31;
    const int half = lane >> 4;
    const unsigned hmask = half ? 0xFFFF0000u : 0x0000FFFFu;

    // ---- load x tile (transposed + swizzled), init top-k lists ----
    {
        const float* src = g_xn + b0 * 64;
        #pragma unroll
        for (int i = 0; i < 8; ++i) {
            int t  = tid + i * 256;
            int m  = t >> 4;       // local b row
            int c4 = t & 15;       // d chunk (4 d's)
            float4 v = *(const float4*)(src + m * 64 + c4 * 4);
            int base = (((m >> 2) ^ (c4 & 7)) << 2) + (m & 3);
            Xs[(4 * c4 + 0) * 128 + base] = v.x;
            Xs[(4 * c4 + 1) * 128 + base] = v.y;
            Xs[(4 * c4 + 2) * 128 + base] = v.z;
            Xs[(4 * c4 + 3) * 128 + base] = v.w;
        }
        for (int i = tid; i < 2048; i += 256) { tv[i] = -3.0e38f; ti[i] = 0; }
    }

    // ---- main m sweep ----
    for (int tile = 0; tile < M_N / 128; ++tile) {
        const int mbase = tile * 128;
        __syncthreads();   // previous tile's reads done before overwrite

        // load K tile (transposed + swizzled), pre-scaled by inverse norm
        {
            const float* src = Kg + (size_t)(q * M_N + mbase) * 64;
            const float* kiv = g_kinv + q * M_N + mbase;
            #pragma unroll
            for (int i = 0; i < 8; ++i) {
                int t  = tid + i * 256;
                int m  = t >> 4;
                int c4 = t & 15;
                float4 v = *(const float4*)(src + m * 64 + c4 * 4);
                float ki = kiv[m];
                int base = (((m >> 2) ^ (c4 & 7)) << 2) + (m & 3);
                Ks[(4 * c4 + 0) * 128 + base] = v.x * ki;
                Ks[(4 * c4 + 1) * 128 + base] = v.y * ki;
                Ks[(4 * c4 + 2) * 128 + base] = v.z * ki;
                Ks[(4 * c4 + 3) * 128 + base] = v.w * ki;
            }
        }
        __syncthreads();

        // compute 8x8 micro-tile of responses
        float acc[8][8];
        #pragma unroll
        for (int j = 0; j < 8; ++j)
            #pragma unroll
            for (int jj = 0; jj < 8; ++jj) acc[j][jj] = 0.0f;

        #pragma unroll 1
        for (int d4 = 0; d4 < 16; ++d4) {
            const int sw = d4 & 7;
            const float* Xr = Xs + d4 * 512;
            const float* Kr = Ks + d4 * 512;
            const int ax = (ty ^ sw) << 2;
            const int bx = (tx ^ sw) << 2;
            #pragma unroll
            for (int e = 0; e < 4; ++e) {
                const float* X = Xr + e * 128;
                const float* Kk = Kr + e * 128;
                float4 a0 = *(const float4*)(X + ax);
                float4 a1 = *(const float4*)(X + ax + 64);
                float4 bb0 = *(const float4*)(Kk + bx);
                float4 bb1 = *(const float4*)(Kk + bx + 64);
                float a[8] = {a0.x, a0.y, a0.z, a0.w, a1.x, a1.y, a1.z, a1.w};
                float b[8] = {bb0.x, bb0.y, bb0.z, bb0.w, bb1.x, bb1.y, bb1.z, bb1.w};
                #pragma unroll
                for (int j = 0; j < 8; ++j)
                    #pragma unroll
                    for (int jj = 0; jj < 8; ++jj)
                        acc[j][jj] += a[j] * b[jj];
            }
        }

        // ---- streaming top-16 update (ballot-guarded rare inserts) ----
        #pragma unroll 1
        for (int j = 0; j < 8; ++j) {
            const int r = (j < 4) ? (ty * 4 + j) : (64 + ty * 4 + (j - 4));
            float* tvr = tv + r * 16;
            int*   tir = ti + r * 16;
            float th = tvr[15];
            bool cand = false;
            #pragma unroll
            for (int jj = 0; jj < 8; ++jj) cand |= (acc[j][jj] > th);
            unsigned bal = __ballot_sync(hmask, cand);
            bal = (bal >> (16 * half)) & 0xFFFFu;
            while (bal) {
                int g = __ffs(bal) - 1;
                bal &= bal - 1;
                if (tx == g) {
                    #pragma unroll
                    for (int jj = 0; jj < 8; ++jj) {
                        float v = acc[j][jj];
                        if (v > tvr[15]) {
                            int c   = (jj < 4) ? (tx * 4 + jj) : (64 + tx * 4 + (jj - 4));
                            int idx = mbase + c;
                            int pos = 15;
                            while (pos > 0 && tvr[pos - 1] < v) {
                                tvr[pos] = tvr[pos - 1];
                                tir[pos] = tir[pos - 1];
                                --pos;
                            }
                            tvr[pos] = v;
                            tir[pos] = idx;
                        }
                    }
                }
                __syncwarp(hmask);
            }
        }
    }

    // ---- finalize: softmax over top-16 + gather-combine from M ----
    __syncwarp(hmask);
    const float* Mq = Mg + (size_t)q * M_N * 64;
    #pragma unroll 1
    for (int j = 0; j < 8; ++j) {
        const int r = (j < 4) ? (ty * 4 + j) : (64 + ty * 4 + (j - 4));
        float* tvr = tv + r * 16;
        int*   tir = ti + r * 16;

        float v  = tvr[tx];            // lane tx owns entry tx
        float mx = tvr[0];             // sorted desc -> max
        float e  = expf(SCALE_A * (v - mx));
        float ssum = e;
        #pragma unroll
        for (int o = 8; o; o >>= 1) ssum += __shfl_xor_sync(hmask, ssum, o);
        float alpha = e / ssum;
        __syncwarp(hmask);             // all reads of tvr done before overwrite
        tvr[tx] = alpha;
        __syncwarp(hmask);

        float4 o4 = make_float4(0.f, 0.f, 0.f, 0.f);
        #pragma unroll
        for (int k = 0; k < K_TOP; ++k) {
            float a  = tvr[k];
            int   id = tir[k];
            float4 mv = *(const float4*)(Mq + (size_t)id * 64 + tx * 4);
            o4.x += a * mv.x;
            o4.y += a * mv.y;
            o4.z += a * mv.z;
            o4.w += a * mv.w;
        }
        *(float4*)(out + ((size_t)(b0 + r) * Q_N + q) * 64 + tx * 4) = o4;
    }
}

// ---------------------------------------------------------------------------
extern "C" void kernel_launch(void* const* d_in, const int* in_sizes, int n_in,
                              void* d_out, int out_size)
{
    const float* x = (const float*)d_in[0];   // [1024, 64]
    const float* K = (const float*)d_in[1];   // [32, 4096, 64]
    const float* M = (const float*)d_in[2];   // [32, 4096, 64]
    float* out = (float*)d_out;               // [1024, 32, 64]

    (void)in_sizes; (void)n_in; (void)out_size;

    norm_x_kernel<<<B_N / 8, 256>>>(x);
    kinv_kernel<<<(Q_N * M_N) / 8, 256>>>(K);

    cudaFuncSetAttribute(cnu_main_kernel,
                         cudaFuncAttributeMaxDynamicSharedMemorySize, 81920);
    cnu_main_kernel<<<dim3(B_N / 128, Q_N), 256, 81920>>>(K, M, out);
}